// round 12
// baseline (speedup 1.0000x reference)
#include <cuda_runtime.h>
#include <cuda_fp16.h>
#include <cstdint>
#include <math.h>

#define BATCH 32
#define LSEQ  512
#define DDIM  768

// scratch: Yt[b][d][l] = fp16( sqrt(w[b,l]) * x[b,l,d] ), K(=l)-major
__device__ __align__(1024) __half g_yt[(size_t)BATCH * DDIM * LSEQ];
__device__ float g_sw[BATCH * LSEQ];

// upper-triangle tile map: 128-row tile ti (0..5) x 64-col tile tj (0..11), tj >= 2*ti
__device__ const unsigned char TI_MAP[42] = {
    0,0,0,0,0,0,0,0,0,0,0,0, 1,1,1,1,1,1,1,1,1,1, 2,2,2,2,2,2,2,2,
    3,3,3,3,3,3, 4,4,4,4, 5,5};
__device__ const unsigned char TJ_MAP[42] = {
    0,1,2,3,4,5,6,7,8,9,10,11, 2,3,4,5,6,7,8,9,10,11, 4,5,6,7,8,9,10,11,
    6,7,8,9,10,11, 8,9,10,11, 10,11};

// ---------------------------------------------------------------------------
__device__ __forceinline__ uint32_t smem_u32(const void* p) {
    uint32_t a;
    asm("{ .reg .u64 t; cvta.to.shared.u64 t, %1; cvt.u32.u64 %0, t; }" : "=r"(a) : "l"(p));
    return a;
}

// logical rows x 32 halfs (64B); 2 rows per 128B physical row, XOR swizzle
__device__ __forceinline__ uint32_t sw_off(int r, int c) {
    uint32_t pr = (uint32_t)r >> 1;
    uint32_t ch = (uint32_t)(((r & 1) << 2) + c) ^ (pr & 7u);
    return pr * 128u + ch * 16u;
}

#define CP_ASYNC16(dst, src) \
    asm volatile("cp.async.cg.shared.global [%0], [%1], 16;" :: "r"(dst), "l"(src))
#define CP_COMMIT() asm volatile("cp.async.commit_group;" ::: "memory")
#define CP_WAIT2()  asm volatile("cp.async.wait_group 2;" ::: "memory")
#define CP_WAIT0()  asm volatile("cp.async.wait_group 0;" ::: "memory")

__device__ __forceinline__ void ldsm4(uint32_t* r, uint32_t a) {
    asm volatile("ldmatrix.sync.aligned.m8n8.x4.shared.b16 {%0,%1,%2,%3}, [%4];"
                 : "=r"(r[0]), "=r"(r[1]), "=r"(r[2]), "=r"(r[3]) : "r"(a));
}

__device__ __forceinline__ void mma_f16(float* d, const uint32_t* a, uint32_t b0, uint32_t b1) {
    asm volatile("mma.sync.aligned.m16n8k16.row.col.f32.f16.f16.f32 "
                 "{%0,%1,%2,%3}, {%4,%5,%6,%7}, {%8,%9}, {%0,%1,%2,%3};"
                 : "+f"(d[0]), "+f"(d[1]), "+f"(d[2]), "+f"(d[3])
                 : "r"(a[0]), "r"(a[1]), "r"(a[2]), "r"(a[3]), "r"(b0), "r"(b1));
}

// ---------------------------------------------------------------------------
// Kernel 1: g_sw[b,l] = (1e-5 + sum_d x^2)^(1/4)
// ---------------------------------------------------------------------------
__global__ void weight_kernel(const float* __restrict__ x) {
    int row  = blockIdx.x * 8 + (threadIdx.x >> 5);
    int lane = threadIdx.x & 31;
    const float4* p = (const float4*)(x + (size_t)row * DDIM);
    float s = 0.f;
#pragma unroll
    for (int i = 0; i < DDIM / 128; i++) {
        float4 v = p[lane + 32 * i];
        s += v.x * v.x + v.y * v.y + v.z * v.z + v.w * v.w;
    }
#pragma unroll
    for (int o = 16; o; o >>= 1) s += __shfl_xor_sync(0xffffffffu, s, o);
    if (lane == 0) g_sw[row] = sqrtf(sqrtf(1e-5f + s));
}

// ---------------------------------------------------------------------------
// Kernel 2: streaming convert+transpose. Reads each x element once (L2-hot).
// ---------------------------------------------------------------------------
__global__ __launch_bounds__(256)
void convert_kernel(const float* __restrict__ x) {
    __shared__ float t[64][33];          // [l_local][d_local]
    const int b  = blockIdx.z;
    const int d0 = blockIdx.x * 32;
    const int l0 = blockIdx.y * 64;
    const int lane = threadIdx.x & 31;
    const int wid  = threadIdx.x >> 5;
    const float* xb = x + (size_t)b * LSEQ * DDIM;
    __half* yb = g_yt + (size_t)b * DDIM * LSEQ;

#pragma unroll
    for (int k = 0; k < 8; k++) {
        int li = wid + 8 * k;
        t[li][lane] = xb[(size_t)(l0 + li) * DDIM + d0 + lane] * g_sw[b * LSEQ + l0 + li];
    }
    __syncthreads();
#pragma unroll
    for (int r = 0; r < 4; r++) {
        int dl = wid * 4 + r;
        __half2 h = __floats2half2_rn(t[2 * lane][dl], t[2 * lane + 1][dl]);
        *(__half2*)(yb + (size_t)(d0 + dl) * LSEQ + l0 + 2 * lane) = h;
    }
}

// ---------------------------------------------------------------------------
// Kernel 3: C = Yt Yt^T, fp16 HMMA. Tile 128x64, warp tile 32x32, 8 warps,
// 3-stage cp.async, 4 CTAs/SM (reg-dieted). Mirror written unconditionally.
// ---------------------------------------------------------------------------
#define STAGE_BYTES 12288            // A 8KB + B 4KB
#define NSTAGE 3
#define SMEM_NEED (NSTAGE * STAGE_BYTES + 1024)

__global__ __launch_bounds__(256, 4)
void gram_mma_kernel(float* __restrict__ out) {
    extern __shared__ char dyn[];
    const int ti = TI_MAP[blockIdx.x];       // 128-row tile
    const int tj = TJ_MAP[blockIdx.x];       // 64-col tile
    const int b  = blockIdx.y;

    const int tid = threadIdx.x, lane = tid & 31, wid = tid >> 5;
    const int wm = wid & 3, wn = wid >> 2;   // 4 x 2 warp grid

    uint32_t raw   = smem_u32(dyn);
    uint32_t sbase = (raw + 1023u) & ~1023u;

    const size_t ybase = (size_t)b * DDIM * LSEQ;

    // pre-advanced global pointers for cp.async (bumped +64B per k-chunk)
    const int lrow = tid >> 2;          // 0..63
    const int lc   = tid & 3;
    const char* pA0 = (const char*)(g_yt + ybase + (size_t)ti * 128 * LSEQ)
                      + (size_t)lrow * 1024 + lc * 16;
    const char* pA1 = pA0 + 64 * 1024;
    const char* pB  = (const char*)(g_yt + ybase + (size_t)tj * 64 * LSEQ)
                      + (size_t)lrow * 1024 + lc * 16;

    // stage-relative smem store offsets
    const uint32_t oA0 = sw_off(lrow, lc);
    const uint32_t oA1 = sw_off(lrow + 64, lc);
    const uint32_t oB  = 8192u + sw_off(lrow, lc);

    // ldsm smem offsets (stage-relative); ks=1 versions are ^32 (XOR-swizzle identity)
    const int arow = wm * 32 + ((lane >> 3) & 1) * 8 + (lane & 7);
    const int brow = wn * 32 + ((lane >> 3) & 1) * 8 + (lane & 7);
    const int ac0  = (lane >> 4);            // 0 or 1
    const uint32_t la0 = sw_off(arow, ac0);
    const uint32_t la1 = sw_off(arow + 16, ac0);
    const uint32_t lb0 = 8192u + sw_off(brow, ac0);
    const uint32_t lb1 = 8192u + sw_off(brow + 16, ac0);

    float acc[2][4][4];
#pragma unroll
    for (int i = 0; i < 2; i++)
#pragma unroll
        for (int j = 0; j < 4; j++)
#pragma unroll
            for (int k = 0; k < 4; k++) acc[i][j][k] = 0.f;

    const int NCH = LSEQ / 32;          // 16

#define ISSUE(st)                                                \
    do {                                                         \
        uint32_t sb_ = sbase + (st) * STAGE_BYTES;               \
        CP_ASYNC16(sb_ + oA0, pA0);                              \
        CP_ASYNC16(sb_ + oA1, pA1);                              \
        CP_ASYNC16(sb_ + oB,  pB);                               \
        pA0 += 64; pA1 += 64; pB += 64;                          \
    } while (0)

    ISSUE(0); CP_COMMIT();
    ISSUE(1); CP_COMMIT();

    for (int it = 0; it < NCH; it++) {
        if (it + 2 < NCH) {
            ISSUE((it + 2) % NSTAGE);
            CP_COMMIT();
            CP_WAIT2();
        } else {
            CP_WAIT0();
        }
        __syncthreads();

        uint32_t sb = sbase + (it % NSTAGE) * STAGE_BYTES;
#pragma unroll
        for (int ks = 0; ks < 2; ks++) {
            const uint32_t kx = ks ? 32u : 0u;
            uint32_t ah[2][4], bh[2][4];
            ldsm4(ah[0], sb + (la0 ^ kx));
            ldsm4(ah[1], sb + (la1 ^ kx));
            ldsm4(bh[0], sb + (lb0 ^ kx));
            ldsm4(bh[1], sb + (lb1 ^ kx));
#pragma unroll
            for (int mt = 0; mt < 2; mt++)
#pragma unroll
                for (int q = 0; q < 4; q++)
                    mma_f16(acc[mt][q], ah[mt], bh[q >> 1][q & 1], bh[q >> 1][(q & 1) + 2]);
        }
        __syncthreads();
    }

    float* ob = out + (size_t)b * DDIM * DDIM;

    // direct write: rows ti*128.., cols tj*64..
    const int r0 = ti * 128 + wm * 32 + (lane >> 2);
    const int c0 = tj * 64 + wn * 32 + (lane & 3) * 2;
#pragma unroll
    for (int mt = 0; mt < 2; mt++)
#pragma unroll
        for (int q = 0; q < 4; q++) {
            int r = r0 + mt * 16;
            int c = c0 + q * 8;
            *(float2*)(ob + (size_t)r * DDIM + c)       = make_float2(acc[mt][q][0], acc[mt][q][1]);
            *(float2*)(ob + (size_t)(r + 8) * DDIM + c) = make_float2(acc[mt][q][2], acc[mt][q][3]);
        }

    // mirror write (always; diagonal overlaps store identical values)
    {
        float (*T)[132] = (float (*)[132])(dyn + (sbase - raw));  // 64 x 132 floats
#pragma unroll
        for (int mt = 0; mt < 2; mt++)
#pragma unroll
            for (int q = 0; q < 4; q++) {
                int lcol = wn * 32 + q * 8 + (lane & 3) * 2;
                int grow = wm * 32 + mt * 16 + (lane >> 2);
                T[lcol][grow]         = acc[mt][q][0];
                T[lcol + 1][grow]     = acc[mt][q][1];
                T[lcol][grow + 8]     = acc[mt][q][2];
                T[lcol + 1][grow + 8] = acc[mt][q][3];
            }
        __syncthreads();
#pragma unroll
        for (int u = 0; u < 8; u++) {
            int v  = tid + u * 256;          // 0..2047
            int rr = v >> 5;                 // 0..63
            int cc = (v & 31) * 4;           // 0..124
            float4 val = *(float4*)&T[rr][cc];
            *(float4*)(ob + (size_t)(tj * 64 + rr) * DDIM + ti * 128 + cc) = val;
        }
    }
}

// ---------------------------------------------------------------------------
extern "C" void kernel_launch(void* const* d_in, const int* in_sizes, int n_in,
                              void* d_out, int out_size) {
    const float* x = (const float*)d_in[0];
    float* out = (float*)d_out;

    weight_kernel<<<BATCH * LSEQ / 8, 256>>>(x);

    dim3 cgrid(DDIM / 32, LSEQ / 64, BATCH);     // (24, 8, 32)
    convert_kernel<<<cgrid, 256>>>(x);

    cudaFuncSetAttribute(gram_mma_kernel, cudaFuncAttributeMaxDynamicSharedMemorySize, SMEM_NEED);
    dim3 ggrid(42, BATCH);                       // 1344 blocks
    gram_mma_kernel<<<ggrid, 256, SMEM_NEED>>>(out);
}

// round 17
// speedup vs baseline: 1.0951x; 1.0951x over previous
#include <cuda_runtime.h>
#include <cuda_fp16.h>
#include <cstdint>
#include <math.h>

#define BATCH 32
#define LSEQ  512
#define DDIM  768

// scratch: Yt[b][d][l] = fp16( sqrt(w[b,l]) * x[b,l,d] ), K(=l)-major
__device__ __align__(1024) __half g_yt[(size_t)BATCH * DDIM * LSEQ];

// upper-triangle tile map: 128-row tile ti (0..5) x 64-col tile tj (0..11), tj >= 2*ti
__device__ const unsigned char TI_MAP[42] = {
    0,0,0,0,0,0,0,0,0,0,0,0, 1,1,1,1,1,1,1,1,1,1, 2,2,2,2,2,2,2,2,
    3,3,3,3,3,3, 4,4,4,4, 5,5};
__device__ const unsigned char TJ_MAP[42] = {
    0,1,2,3,4,5,6,7,8,9,10,11, 2,3,4,5,6,7,8,9,10,11, 4,5,6,7,8,9,10,11,
    6,7,8,9,10,11, 8,9,10,11, 10,11};

// ---------------------------------------------------------------------------
__device__ __forceinline__ uint32_t smem_u32(const void* p) {
    uint32_t a;
    asm("{ .reg .u64 t; cvta.to.shared.u64 t, %1; cvt.u32.u64 %0, t; }" : "=r"(a) : "l"(p));
    return a;
}

// logical rows x 32 halfs (64B); 2 rows per 128B physical row, XOR swizzle
__device__ __forceinline__ uint32_t sw_off(int r, int c) {
    uint32_t pr = (uint32_t)r >> 1;
    uint32_t ch = (uint32_t)(((r & 1) << 2) + c) ^ (pr & 7u);
    return pr * 128u + ch * 16u;
}

#define CP_ASYNC16(dst, src) \
    asm volatile("cp.async.cg.shared.global [%0], [%1], 16;" :: "r"(dst), "l"(src))
#define CP_COMMIT() asm volatile("cp.async.commit_group;" ::: "memory")
#define CP_WAIT2()  asm volatile("cp.async.wait_group 2;" ::: "memory")
#define CP_WAIT0()  asm volatile("cp.async.wait_group 0;" ::: "memory")

__device__ __forceinline__ void ldsm4(uint32_t* r, uint32_t a) {
    asm volatile("ldmatrix.sync.aligned.m8n8.x4.shared.b16 {%0,%1,%2,%3}, [%4];"
                 : "=r"(r[0]), "=r"(r[1]), "=r"(r[2]), "=r"(r[3]) : "r"(a));
}

__device__ __forceinline__ void mma_f16(float* d, const uint32_t* a, uint32_t b0, uint32_t b1) {
    asm volatile("mma.sync.aligned.m16n8k16.row.col.f32.f16.f16.f32 "
                 "{%0,%1,%2,%3}, {%4,%5,%6,%7}, {%8,%9}, {%0,%1,%2,%3};"
                 : "+f"(d[0]), "+f"(d[1]), "+f"(d[2]), "+f"(d[3])
                 : "r"(a[0]), "r"(a[1]), "r"(a[2]), "r"(a[3]), "r"(b0), "r"(b1));
}

// ---------------------------------------------------------------------------
// Fused prep: one global read of x. 32 tokens/block staged in smem (fp32),
// norms accumulated during the load; scale+transpose+fp16 written from smem.
// smem pitch 769 floats -> phase-2 column reads hit distinct banks.
// ---------------------------------------------------------------------------
#define PREP_PITCH 769
#define PREP_SMEM  (32 * PREP_PITCH * 4)     // 98432 B

__global__ __launch_bounds__(256, 2)
void prep_kernel(const float* __restrict__ x) {
    extern __shared__ float s[];             // [32][PREP_PITCH]
    __shared__ float sw[32];
    const int b  = blockIdx.y;
    const int l0 = blockIdx.x * 32;
    const int lane = threadIdx.x & 31;
    const int wid  = threadIdx.x >> 5;

    // phase 1: stream 4 tokens per warp into smem, fold in norm accumulation
#pragma unroll
    for (int t = 0; t < 4; t++) {
        const int li = wid * 4 + t;
        const float4* p = (const float4*)(x + ((size_t)b * LSEQ + l0 + li) * DDIM);
        float* row = s + li * PREP_PITCH;
        float acc = 0.f;
#pragma unroll
        for (int i = 0; i < DDIM / 128; i++) {        // 6
            float4 v = p[lane + 32 * i];
            int c = lane * 4 + i * 128;
            row[c] = v.x; row[c + 1] = v.y; row[c + 2] = v.z; row[c + 3] = v.w;
            acc += v.x * v.x + v.y * v.y + v.z * v.z + v.w * v.w;
        }
#pragma unroll
        for (int o = 16; o; o >>= 1) acc += __shfl_xor_sync(0xffffffffu, acc, o);
        if (lane == 0) sw[li] = sqrtf(sqrtf(1e-5f + acc));
    }
    __syncthreads();

    // phase 2: Yt[d][l0..l0+31] as half2, straight from smem
    __half* yb = g_yt + (size_t)b * DDIM * LSEQ;
#pragma unroll 4
    for (int j = 0; j < (DDIM * 16) / 256; j++) {     // 48
        int idx = threadIdx.x + 256 * j;              // 0..12287
        int d   = idx >> 4;
        int lp  = idx & 15;
        float y0 = s[(2 * lp)     * PREP_PITCH + d] * sw[2 * lp];
        float y1 = s[(2 * lp + 1) * PREP_PITCH + d] * sw[2 * lp + 1];
        *(__half2*)(yb + (size_t)d * LSEQ + l0 + 2 * lp) = __floats2half2_rn(y0, y1);
    }
}

// ---------------------------------------------------------------------------
// Gram: C = Yt Yt^T, fp16 HMMA. Tile 128x64, warp tile 32x32, 8 warps,
// 3-stage cp.async, 3 CTAs/SM. Mirror written unconditionally (symmetric).
// (R6 configuration — best measured.)
// ---------------------------------------------------------------------------
#define STAGE_BYTES 12288            // A 8KB + B 4KB
#define NSTAGE 3
#define SMEM_NEED (NSTAGE * STAGE_BYTES + 1024)

__global__ __launch_bounds__(256, 3)
void gram_mma_kernel(float* __restrict__ out) {
    extern __shared__ char dyn[];
    const int ti = TI_MAP[blockIdx.x];       // 128-row tile
    const int tj = TJ_MAP[blockIdx.x];       // 64-col tile
    const int b  = blockIdx.y;

    const int tid = threadIdx.x, lane = tid & 31, wid = tid >> 5;
    const int wm = wid & 3, wn = wid >> 2;   // 4 x 2 warp grid

    uint32_t raw   = smem_u32(dyn);
    uint32_t sbase = (raw + 1023u) & ~1023u;

    const size_t ybase = (size_t)b * DDIM * LSEQ;
    const char* srcA = (const char*)(g_yt + ybase + (size_t)ti * 128 * LSEQ);
    const char* srcB = (const char*)(g_yt + ybase + (size_t)tj * 64 * LSEQ);

    float acc[2][4][4];
#pragma unroll
    for (int i = 0; i < 2; i++)
#pragma unroll
        for (int j = 0; j < 4; j++)
#pragma unroll
            for (int k = 0; k < 4; k++) acc[i][j][k] = 0.f;

    const int lrow = tid >> 2;          // 0..63
    const int lc   = tid & 3;
    const int NCH  = LSEQ / 32;         // 16

#define ISSUE(st, it_)                                                                   \
    do {                                                                                 \
        uint32_t sb_ = sbase + (st) * STAGE_BYTES;                                       \
        int ko_ = (it_) * 64;                                                            \
        CP_ASYNC16(sb_ + sw_off(lrow, lc),          srcA + (size_t)lrow * 1024 + ko_ + lc * 16); \
        CP_ASYNC16(sb_ + sw_off(lrow + 64, lc),     srcA + (size_t)(lrow + 64) * 1024 + ko_ + lc * 16); \
        CP_ASYNC16(sb_ + 8192 + sw_off(lrow, lc),   srcB + (size_t)lrow * 1024 + ko_ + lc * 16); \
    } while (0)

    ISSUE(0, 0); CP_COMMIT();
    ISSUE(1, 1); CP_COMMIT();

    const int arow = wm * 32 + ((lane >> 3) & 1) * 8 + (lane & 7);
    const int brow = wn * 32 + ((lane >> 3) & 1) * 8 + (lane & 7);

    for (int it = 0; it < NCH; it++) {
        if (it + 2 < NCH) {
            ISSUE((it + 2) % NSTAGE, it + 2);
            CP_COMMIT();
            CP_WAIT2();
        } else {
            CP_WAIT0();
        }
        __syncthreads();

        uint32_t sb = sbase + (it % NSTAGE) * STAGE_BYTES;
#pragma unroll
        for (int ks = 0; ks < 2; ks++) {
            const int ac = ks * 2 + (lane >> 4);
            uint32_t ah[2][4], bh[2][4];
            ldsm4(ah[0], sb + sw_off(arow, ac));
            ldsm4(ah[1], sb + sw_off(arow + 16, ac));
            ldsm4(bh[0], sb + 8192 + sw_off(brow, ac));
            ldsm4(bh[1], sb + 8192 + sw_off(brow + 16, ac));
#pragma unroll
            for (int mt = 0; mt < 2; mt++)
#pragma unroll
                for (int q = 0; q < 4; q++)
                    mma_f16(acc[mt][q], ah[mt], bh[q >> 1][q & 1], bh[q >> 1][(q & 1) + 2]);
        }
        __syncthreads();
    }

    float* ob = out + (size_t)b * DDIM * DDIM;

    // direct write: rows ti*128.., cols tj*64..
    const int r0 = ti * 128 + wm * 32 + (lane >> 2);
    const int c0 = tj * 64 + wn * 32 + (lane & 3) * 2;
#pragma unroll
    for (int mt = 0; mt < 2; mt++)
#pragma unroll
        for (int q = 0; q < 4; q++) {
            int r = r0 + mt * 16;
            int c = c0 + q * 8;
            *(float2*)(ob + (size_t)r * DDIM + c)       = make_float2(acc[mt][q][0], acc[mt][q][1]);
            *(float2*)(ob + (size_t)(r + 8) * DDIM + c) = make_float2(acc[mt][q][2], acc[mt][q][3]);
        }

    // mirror write (always; diagonal overlaps store identical values)
    {
        float (*T)[132] = (float (*)[132])(dyn + (sbase - raw));  // 64 x 132 floats
#pragma unroll
        for (int mt = 0; mt < 2; mt++)
#pragma unroll
            for (int q = 0; q < 4; q++) {
                int lcol = wn * 32 + q * 8 + (lane & 3) * 2;
                int grow = wm * 32 + mt * 16 + (lane >> 2);
                T[lcol][grow]         = acc[mt][q][0];
                T[lcol + 1][grow]     = acc[mt][q][1];
                T[lcol][grow + 8]     = acc[mt][q][2];
                T[lcol + 1][grow + 8] = acc[mt][q][3];
            }
        __syncthreads();
#pragma unroll
        for (int u = 0; u < 8; u++) {
            int v  = tid + u * 256;          // 0..2047
            int rr = v >> 5;                 // 0..63
            int cc = (v & 31) * 4;           // 0..124
            float4 val = *(float4*)&T[rr][cc];
            *(float4*)(ob + (size_t)(tj * 64 + rr) * DDIM + ti * 128 + cc) = val;
        }
    }
}

// ---------------------------------------------------------------------------
extern "C" void kernel_launch(void* const* d_in, const int* in_sizes, int n_in,
                              void* d_out, int out_size) {
    const float* x = (const float*)d_in[0];
    float* out = (float*)d_out;

    cudaFuncSetAttribute(prep_kernel, cudaFuncAttributeMaxDynamicSharedMemorySize, PREP_SMEM);
    dim3 pgrid(LSEQ / 32, BATCH);                // (16, 32) = 512 blocks
    prep_kernel<<<pgrid, 256, PREP_SMEM>>>(x);

    cudaFuncSetAttribute(gram_mma_kernel, cudaFuncAttributeMaxDynamicSharedMemorySize, SMEM_NEED);
    dim3 ggrid(42, BATCH);                       // 1344 blocks
    gram_mma_kernel<<<ggrid, 256, SMEM_NEED>>>(out);
}